// round 16
// baseline (speedup 1.0000x reference)
#include <cuda_runtime.h>
#include <cuda_bf16.h>
#include <cuda_fp16.h>
#include <cstdint>

// ---------------- problem constants ----------------
#define B_     2
#define S_     2048
#define H_     2048
#define NH_    16
#define HD_    128
#define CACHE_ 2048
#define KV_    4096           // CACHE_ + S_
#define M_     4096           // B_*S_
#define KDIM_  2048           // H_

#define SCALE_ 0.08838834764831845f   // 1/sqrt(128)

// fp16 scratch (allocation-free rule: __device__ globals)
static __device__ __half sXh[(size_t)M_ * KDIM_];
static __device__ __half sXl[(size_t)M_ * KDIM_];
static __device__ __half sWq[(size_t)H_ * KDIM_];
static __device__ __half sWk[(size_t)H_ * KDIM_];
static __device__ __half sWv[(size_t)H_ * KDIM_];
static __device__ __half sWo[(size_t)H_ * KDIM_];

// attention operands: plain fp16
static __device__ __half sQf[(size_t)B_ * NH_ * S_ * HD_];
static __device__ __half sKf[(size_t)B_ * NH_ * KV_ * HD_];
static __device__ __half sVf[(size_t)B_ * NH_ * KV_ * HD_];
// attention output: fp16 2-term split for the output projection
static __device__ __half sAh[(size_t)M_ * KDIM_];
static __device__ __half sAl[(size_t)M_ * KDIM_];

// ---------------- helpers ----------------
__device__ __forceinline__ uint32_t smem_u32(const void* p) {
    uint32_t a;
    asm("{ .reg .u64 t; cvta.to.shared.u64 t, %1; cvt.u32.u64 %0, t; }" : "=r"(a) : "l"(p));
    return a;
}

#define LDSM4(r0,r1,r2,r3,addr) \
    asm volatile("ldmatrix.sync.aligned.m8n8.x4.shared.b16 {%0,%1,%2,%3}, [%4];" \
        : "=r"(r0),"=r"(r1),"=r"(r2),"=r"(r3) : "r"(addr))

#define LDSM4T(r0,r1,r2,r3,addr) \
    asm volatile("ldmatrix.sync.aligned.m8n8.x4.trans.shared.b16 {%0,%1,%2,%3}, [%4];" \
        : "=r"(r0),"=r"(r1),"=r"(r2),"=r"(r3) : "r"(addr))

#define MMA16816H(c, a, b) \
    asm volatile("mma.sync.aligned.m16n8k16.row.col.f32.f16.f16.f32 " \
        "{%0,%1,%2,%3}, {%4,%5,%6,%7}, {%8,%9}, {%0,%1,%2,%3};" \
        : "+f"((c)[0]),"+f"((c)[1]),"+f"((c)[2]),"+f"((c)[3]) \
        : "r"((a)[0]),"r"((a)[1]),"r"((a)[2]),"r"((a)[3]), "r"((b)[0]),"r"((b)[1]))

#define CP_ASYNC16(saddr, gaddr) \
    asm volatile("cp.async.cg.shared.global [%0], [%1], 16;" :: "r"(saddr), "l"(gaddr))
#define CP_COMMIT() asm volatile("cp.async.commit_group;" ::: "memory")
#define CP_WAIT0()  asm volatile("cp.async.wait_group 0;" ::: "memory")

__device__ __forceinline__ void store_split_h(__half* dh, __half* dl,
                                              size_t idx, float2 v) {
    __half h0 = __float2half_rn(v.x), h1 = __float2half_rn(v.y);
    __half l0 = __float2half_rn(v.x - __half2float(h0));
    __half l1 = __float2half_rn(v.y - __half2float(h1));
    __half2 hh; hh.x = h0; hh.y = h1;
    __half2 ll; ll.x = l0; ll.y = l1;
    *(__half2*)(dh + idx) = hh;
    *(__half2*)(dl + idx) = ll;
}

// ---------------- cache splice (+ fp16 copies for attention) ----------------
__global__ void copy_cache_kernel(const float4* __restrict__ kc,
                                  const float4* __restrict__ vc,
                                  float4* __restrict__ ko,
                                  float4* __restrict__ vo,
                                  uint2* __restrict__ kf, uint2* __restrict__ vf) {
    int i = blockIdx.x * blockDim.x + threadIdx.x;
    int chunk = i >> 16;
    int rem   = i & 65535;
    size_t d = (size_t)chunk * (KV_ * HD_ / 4) + rem;
    float4 kk = kc[i];
    float4 vv = vc[i];
    ko[d] = kk;
    vo[d] = vv;
    __half kh4[4] = {__float2half_rn(kk.x), __float2half_rn(kk.y),
                     __float2half_rn(kk.z), __float2half_rn(kk.w)};
    __half vh4[4] = {__float2half_rn(vv.x), __float2half_rn(vv.y),
                     __float2half_rn(vv.z), __float2half_rn(vv.w)};
    kf[d] = *(uint2*)kh4;
    vf[d] = *(uint2*)vh4;
}

// ---------------- fp32 -> fp16 hi/lo split (activations) ----------------
__global__ void split_h_kernel(const float4* __restrict__ src,
                               uint2* __restrict__ hi, uint2* __restrict__ lo) {
    int i = blockIdx.x * blockDim.x + threadIdx.x;
    float4 v = src[i];
    float f[4] = {v.x, v.y, v.z, v.w};
    __half H[4], L[4];
    #pragma unroll
    for (int j = 0; j < 4; j++) {
        H[j] = __float2half_rn(f[j]);
        L[j] = __float2half_rn(f[j] - __half2float(H[j]));
    }
    hi[i] = *(uint2*)H;
    lo[i] = *(uint2*)L;
}

// fused 4-weight fp32 -> plain fp16 convert
__global__ void convert4_kernel(const float4* s0, const float4* s1,
                                const float4* s2, const float4* s3,
                                uint2* d0, uint2* d1, uint2* d2, uint2* d3) {
    int z = blockIdx.y;
    const float4* s = (z == 0) ? s0 : (z == 1) ? s1 : (z == 2) ? s2 : s3;
    uint2* d = (z == 0) ? d0 : (z == 1) ? d1 : (z == 2) ? d2 : d3;
    int i = blockIdx.x * blockDim.x + threadIdx.x;
    float4 v = s[i];
    __half h[4] = {__float2half_rn(v.x), __float2half_rn(v.y),
                   __float2half_rn(v.z), __float2half_rn(v.w)};
    d[i] = *(uint2*)h;
}

// ---------------- mma.sync fp16 GEMM core (R15-proven) ----------------
// D = (Ah + Al)[M,K] x B[N,K]^T + bias   (A 2-term fp16 split, B plain fp16)
#define GKC      32
#define GNCH     (KDIM_/GKC)           // 64
#define TPAD     40
#define TILE_B   (128*TPAD*2)          // 10240
#define BUF_B    (3*TILE_B)            // 30720 (Ah,Al,B)
#define GT_SMEM  (512 + 2*BUF_B)       // 61952

__device__ __forceinline__
void gemm_core(const __half* __restrict__ Ah, const __half* __restrict__ Al,
               const __half* __restrict__ Bf,
               const float* __restrict__ bias, float* __restrict__ dst,
               __half* __restrict__ df,
               int mode, int Lrow, int off, float scale,
               char* smc, int m0, int n0)
{
    float* s_bias = (float*)smc;
    const uint32_t sbase = smem_u32(smc + 512);

    const int tid = threadIdx.x;
    const int wid = tid >> 5, lane = tid & 31;
    const int wm = (wid & 3) * 32, wn = (wid >> 2) * 32;

    if (tid < 128) s_bias[tid] = bias[n0 + tid];

    const __half* srcAh = Ah + (size_t)m0 * KDIM_;
    const __half* srcAl = Al + (size_t)m0 * KDIM_;
    const __half* srcB  = Bf + (size_t)n0 * KDIM_;

    const int ld_row = tid >> 2;          // 0..127
    const int ld_c16 = tid & 3;           // 16B column
    const int aRow = wm + (lane & 15);
    const uint32_t offA0 = ((uint32_t)(aRow * TPAD + ((lane >> 4) << 3))) * 2u;
    const int bRow = wn + ((lane >> 4) << 3) + (lane & 7);
    const uint32_t offB0 = ((uint32_t)(bRow * TPAD + (((lane >> 3) & 1) << 3))) * 2u;

    float acc[2][4][4];
    #pragma unroll
    for (int i = 0; i < 2; i++)
        #pragma unroll
        for (int j = 0; j < 4; j++)
            #pragma unroll
            for (int q = 0; q < 4; q++) acc[i][j][q] = 0.f;

    auto load_chunk = [&](int buf, int c0) {
        uint32_t sb = sbase + buf * BUF_B;
        uint32_t so = (uint32_t)(ld_row * TPAD + ld_c16 * 8) * 2u;
        size_t go = (size_t)ld_row * KDIM_ + c0 + ld_c16 * 8;
        CP_ASYNC16(sb + 0 * TILE_B + so, srcAh + go);
        CP_ASYNC16(sb + 1 * TILE_B + so, srcAl + go);
        CP_ASYNC16(sb + 2 * TILE_B + so, srcB  + go);
        CP_COMMIT();
    };

    load_chunk(0, 0);

    for (int c = 0; c < GNCH; ++c) {
        CP_WAIT0();
        __syncthreads();
        if (c + 1 < GNCH) load_chunk((c + 1) & 1, (c + 1) * GKC);

        const uint32_t bb = sbase + (c & 1) * BUF_B;
        #pragma unroll
        for (int ks = 0; ks < 2; ++ks) {
            const uint32_t ko_ = ks * 32;
            uint32_t ah[2][4], al[2][4];
            #pragma unroll
            for (int mt = 0; mt < 2; ++mt) {
                LDSM4(ah[mt][0], ah[mt][1], ah[mt][2], ah[mt][3],
                      bb + 0 * TILE_B + offA0 + mt * (16 * TPAD * 2) + ko_);
                LDSM4(al[mt][0], al[mt][1], al[mt][2], al[mt][3],
                      bb + 1 * TILE_B + offA0 + mt * (16 * TPAD * 2) + ko_);
            }
            uint32_t bf[4][2];
            #pragma unroll
            for (int p = 0; p < 2; ++p) {
                uint32_t r0, r1, r2, r3;
                LDSM4(r0, r1, r2, r3,
                      bb + 2 * TILE_B + offB0 + p * (16 * TPAD * 2) + ko_);
                bf[2*p][0] = r0; bf[2*p][1] = r1; bf[2*p+1][0] = r2; bf[2*p+1][1] = r3;
            }
            #pragma unroll
            for (int mt = 0; mt < 2; ++mt)
                #pragma unroll
                for (int nt = 0; nt < 4; ++nt) {
                    MMA16816H(acc[mt][nt], ah[mt], bf[nt]);
                    MMA16816H(acc[mt][nt], al[mt], bf[nt]);
                }
        }
    }
    __syncthreads();

    #pragma unroll
    for (int mt = 0; mt < 2; ++mt) {
        #pragma unroll
        for (int nt = 0; nt < 4; ++nt) {
            float* cc = acc[mt][nt];
            int row0 = m0 + wm + mt * 16 + (lane >> 2);
            int col  = wn + nt * 8 + (lane & 3) * 2;
            float2 v0 = make_float2((cc[0] + s_bias[col]) * scale,
                                    (cc[1] + s_bias[col + 1]) * scale);
            float2 v1 = make_float2((cc[2] + s_bias[col]) * scale,
                                    (cc[3] + s_bias[col + 1]) * scale);
            if (mode == 0) {
                float* p0 = dst + (size_t)row0 * H_ + n0 + col;
                *(float2*)p0 = v0;
                *(float2*)(p0 + (size_t)8 * H_) = v1;
            } else {
                int bb_ = row0 >> 11, s = row0 & (S_ - 1);
                int head = n0 >> 7;
                size_t idx = ((size_t)(bb_ * NH_ + head) * Lrow + off + s) * HD_ + (col & (HD_ - 1));
                size_t idx1 = idx + (size_t)8 * HD_;
                if (mode == 1) {
                    *(float2*)(dst + idx)  = v0;
                    *(float2*)(dst + idx1) = v1;
                }
                *(__half2*)(df + idx)  = __floats2half2_rn(v0.x, v0.y);
                *(__half2*)(df + idx1) = __floats2half2_rn(v1.x, v1.y);
            }
        }
    }
}

__global__ __launch_bounds__(512, 1)
void gemm_qkv(const __half* __restrict__ xh, const __half* __restrict__ xl,
              const __half* __restrict__ wq, const __half* __restrict__ wk,
              const __half* __restrict__ wv,
              const float* __restrict__ bq, const float* __restrict__ bk,
              const float* __restrict__ bv,
              float* __restrict__ ko, float* __restrict__ vo,
              __half* __restrict__ qf, __half* __restrict__ kf, __half* __restrict__ vf)
{
    extern __shared__ char smc[];
    const int z = blockIdx.z;
    const int n0 = blockIdx.x * 128, m0 = blockIdx.y * 128;
    if (z == 0) {
        gemm_core(xh, xl, wq, bq, nullptr, qf, 2, S_, 0, SCALE_, smc, m0, n0);
    } else if (z == 1) {
        gemm_core(xh, xl, wk, bk, ko, kf, 1, KV_, CACHE_, 1.0f, smc, m0, n0);
    } else {
        gemm_core(xh, xl, wv, bv, vo, vf, 1, KV_, CACHE_, 1.0f, smc, m0, n0);
    }
}

__global__ __launch_bounds__(512, 1)
void gemm_out(const __half* __restrict__ Ah, const __half* __restrict__ Al,
              const __half* __restrict__ Bf,
              const float* __restrict__ bias, float* __restrict__ dst)
{
    extern __shared__ char smc[];
    gemm_core(Ah, Al, Bf, bias, dst, nullptr, 0, 0, 0, 1.0f,
              smc, blockIdx.y * 128, blockIdx.x * 128);
}

// ---------------- flash attention via mma.sync, plain fp16 operands ----------------
// R16: KV tile 64 (iters 128->64) — fp16 singles make the register footprint
// feasible (qF 32 + o 64 + sacc 32 in-place-exp + pF 16 ≈ 175 regs; R9's AKT=64
// failure was the 3-term bf16 register blow-up). Halves per-iter serial costs.
#define AKT 64
#define QPITCH 272
#define KOFF   0
#define VOFF   17408
#define MSOFF  34816
#define MPITCH 256                       // 64 floats per mask row
#define STAGE_B 67584                    // K 17408 + V 17408 + mask 32768
#define QBYTES (128*QPITCH)              // 34816
#define QOFF   (2*STAGE_B)               // 135168
#define ATT_SMEM (2*STAGE_B + QBYTES)    // 169984

__global__ __launch_bounds__(256, 1)
void attn_mma(const __half* __restrict__ Qf,
              const __half* __restrict__ Kf,
              const __half* __restrict__ Vf,
              const float* __restrict__ Msk,
              __half* __restrict__ Oh, __half* __restrict__ Ol)
{
    extern __shared__ char sma[];
    const uint32_t sb = smem_u32(sma);

    const int tid = threadIdx.x;
    const int wid = tid >> 5, lane = tid & 31;
    const int qt = blockIdx.x, h = blockIdx.y, b = blockIdx.z;

    const size_t bh_q = ((size_t)(b * NH_ + h) * S_ + qt * 128) * HD_;
    const size_t bh_kv = (size_t)(b * NH_ + h) * KV_ * HD_;
    const float* Mb = Msk + ((size_t)b * S_ + qt * 128) * KV_;

    // --- Q cp.async ---
    {
        int qr = tid >> 1, qc = (tid & 1) * 8;
        const __half* qp = Qf + bh_q + (size_t)qr * HD_ + qc * 8;
        uint32_t d0 = sb + QOFF + qr * QPITCH + qc * 16;
        #pragma unroll
        for (int j = 0; j < 8; j++)
            CP_ASYNC16(d0 + j * 16, qp + j * 8);
    }
    // --- KV + mask stage loader (64 kv rows per stage) ---
    const int kv_row = tid >> 2;          // 0..63
    const int kv_c   = tid & 3;           // 16B chunk base within row
    const int m_row  = tid >> 1;          // 0..127
    const int m_half = tid & 1;           // half-row (32 floats)
    auto issue_stage = [&](int t) {
        uint32_t st = sb + (t & 1) * STAGE_B;
        size_t go = bh_kv + (size_t)(t * AKT + kv_row) * HD_ + kv_c * 8;
        uint32_t so = st + kv_row * QPITCH + kv_c * 16;
        #pragma unroll
        for (int j = 0; j < 4; j++) {
            CP_ASYNC16(so + KOFF + j * 64, Kf + go + j * 32);
            CP_ASYNC16(so + VOFF + j * 64, Vf + go + j * 32);
        }
        const float* mp = Mb + (size_t)m_row * KV_ + t * AKT + m_half * 32;
        uint32_t md = st + MSOFF + m_row * MPITCH + m_half * 128;
        #pragma unroll
        for (int j = 0; j < 8; j++)
            CP_ASYNC16(md + j * 16, mp + j * 4);
    };
    issue_stage(0);
    CP_COMMIT();

    uint32_t qF[8][4];
    float o[16][4];
    #pragma unroll
    for (int i = 0; i < 16; i++)
        #pragma unroll
        for (int j = 0; j < 4; j++) o[i][j] = 0.f;
    float m0r = -1e30f, m1r = -1e30f, l0r = 0.f, l1r = 0.f;

    const uint32_t qAoff = (uint32_t)((wid * 16 + (lane & 15)) * QPITCH + ((lane >> 4) << 3) * 2);
    const uint32_t kBrow = (uint32_t)((((lane >> 4) << 3) + (lane & 7)) * QPITCH + (((lane >> 3) & 1) << 3) * 2);
    const uint32_t vTrow = (uint32_t)(((((lane >> 3) & 1) << 3) + (lane & 7)) * QPITCH + ((lane >> 4) << 3) * 2);

    const int NIT = KV_ / AKT;   // 64
    for (int t = 0; t < NIT; ++t) {
        CP_WAIT0();
        __syncthreads();
        if (t + 1 < NIT) { issue_stage(t + 1); CP_COMMIT(); }

        if (t == 0) {
            #pragma unroll
            for (int ks = 0; ks < 8; ++ks)
                LDSM4(qF[ks][0], qF[ks][1], qF[ks][2], qF[ks][3], sb + QOFF + qAoff + ks * 32);
        }

        const uint32_t st = sb + (t & 1) * STAGE_B;

        // ---- scores: m16 x 64 ----
        float sacc[8][4];
        #pragma unroll
        for (int i = 0; i < 8; i++)
            #pragma unroll
            for (int j = 0; j < 4; j++) sacc[i][j] = 0.f;

        #pragma unroll
        for (int ks = 0; ks < 8; ++ks) {
            #pragma unroll
            for (int nh = 0; nh < 4; ++nh) {
                uint32_t k0, k1, k2, k3;
                LDSM4(k0, k1, k2, k3,
                      st + KOFF + kBrow + nh * 16 * QPITCH + ks * 32);
                uint32_t b0[2] = {k0, k1}, b1[2] = {k2, k3};
                MMA16816H(sacc[2*nh],   qF[ks], b0);
                MMA16816H(sacc[2*nh+1], qF[ks], b1);
            }
        }

        // ---- softmax (fp32, in place; q pre-scaled; add mask) ----
        const uint32_t msb = st + MSOFF + (wid * 16 + (lane >> 2)) * MPITCH + (lane & 3) * 8;
        float rm0 = -1e30f, rm1 = -1e30f;
        #pragma unroll
        for (int nt = 0; nt < 8; ++nt) {
            float2 mv0 = *(const float2*)(sma + (msb + nt * 32 - sb));
            float2 mv1 = *(const float2*)(sma + (msb + nt * 32 + 8 * MPITCH - sb));
            sacc[nt][0] += mv0.x;
            sacc[nt][1] += mv0.y;
            sacc[nt][2] += mv1.x;
            sacc[nt][3] += mv1.y;
            rm0 = fmaxf(rm0, fmaxf(sacc[nt][0], sacc[nt][1]));
            rm1 = fmaxf(rm1, fmaxf(sacc[nt][2], sacc[nt][3]));
        }
        rm0 = fmaxf(rm0, __shfl_xor_sync(0xffffffffu, rm0, 1));
        rm0 = fmaxf(rm0, __shfl_xor_sync(0xffffffffu, rm0, 2));
        rm1 = fmaxf(rm1, __shfl_xor_sync(0xffffffffu, rm1, 1));
        rm1 = fmaxf(rm1, __shfl_xor_sync(0xffffffffu, rm1, 2));
        float nm0 = fmaxf(m0r, rm0), nm1 = fmaxf(m1r, rm1);

        float rs0 = 0.f, rs1 = 0.f;
        #pragma unroll
        for (int nt = 0; nt < 8; ++nt) {
            sacc[nt][0] = __expf(sacc[nt][0] - nm0);
            sacc[nt][1] = __expf(sacc[nt][1] - nm0);
            sacc[nt][2] = __expf(sacc[nt][2] - nm1);
            sacc[nt][3] = __expf(sacc[nt][3] - nm1);
            rs0 += sacc[nt][0] + sacc[nt][1];
            rs1 += sacc[nt][2] + sacc[nt][3];
        }
        rs0 += __shfl_xor_sync(0xffffffffu, rs0, 1);
        rs0 += __shfl_xor_sync(0xffffffffu, rs0, 2);
        rs1 += __shfl_xor_sync(0xffffffffu, rs1, 1);
        rs1 += __shfl_xor_sync(0xffffffffu, rs1, 2);

        // ballot-skip rescale: alpha==1 exactly when max unchanged
        uint32_t need = __ballot_sync(0xffffffffu, (nm0 > m0r) || (nm1 > m1r));
        if (need) {
            float al0 = __expf(m0r - nm0), al1 = __expf(m1r - nm1);
            #pragma unroll
            for (int i = 0; i < 16; i++) {
                o[i][0] *= al0; o[i][1] *= al0;
                o[i][2] *= al1; o[i][3] *= al1;
            }
            l0r = l0r * al0 + rs0;
            l1r = l1r * al1 + rs1;
        } else {
            l0r += rs0;
            l1r += rs1;
        }
        m0r = nm0; m1r = nm1;

        // ---- P -> fp16 A-frags (4 k16 chunks) ----
        uint32_t pF[4][4];
        #pragma unroll
        for (int ks2 = 0; ks2 < 4; ++ks2) {
            #pragma unroll
            for (int half = 0; half < 2; ++half) {
                int nt = 2 * ks2 + half;
                #pragma unroll
                for (int rr = 0; rr < 2; ++rr) {
                    __half2 hp = __floats2half2_rn(sacc[nt][2*rr], sacc[nt][2*rr+1]);
                    pF[ks2][half*2 + rr] = *(uint32_t*)&hp;
                }
            }
        }

        // ---- PV: o[m16][128] += P[m16][64] * V[64][128] ----
        #pragma unroll
        for (int ks2 = 0; ks2 < 4; ++ks2) {
            #pragma unroll
            for (int vb = 0; vb < 8; ++vb) {
                uint32_t h0, h1, h2, h3;
                LDSM4T(h0, h1, h2, h3,
                       st + VOFF + vTrow + ks2 * 16 * QPITCH + vb * 32);
                uint32_t b0[2] = {h0, h1}, b1[2] = {h2, h3};
                MMA16816H(o[2*vb],   pF[ks2], b0);
                MMA16816H(o[2*vb+1], pF[ks2], b1);
            }
        }
    }

    float i0 = 1.0f / l0r, i1 = 1.0f / l1r;
    int r0 = qt * 128 + wid * 16 + (lane >> 2);
    size_t base0 = ((size_t)b * S_ + r0) * H_ + h * HD_ + (lane & 3) * 2;
    size_t base1 = base0 + (size_t)8 * H_;
    #pragma unroll
    for (int nt = 0; nt < 16; ++nt) {
        store_split_h(Oh, Ol, base0 + nt * 8, make_float2(o[nt][0] * i0, o[nt][1] * i0));
        store_split_h(Oh, Ol, base1 + nt * 8, make_float2(o[nt][2] * i1, o[nt][3] * i1));
    }
}

// ---------------- launch ----------------
extern "C" void kernel_launch(void* const* d_in, const int* in_sizes, int n_in,
                              void* d_out, int out_size) {
    (void)in_sizes; (void)n_in; (void)out_size;
    const float* x   = (const float*)d_in[0];
    const float* msk = (const float*)d_in[1];
    const float* kc  = (const float*)d_in[2];
    const float* vc  = (const float*)d_in[3];
    const float* Wq  = (const float*)d_in[4];
    const float* bq  = (const float*)d_in[5];
    const float* Wk  = (const float*)d_in[6];
    const float* bk  = (const float*)d_in[7];
    const float* Wv  = (const float*)d_in[8];
    const float* bv  = (const float*)d_in[9];
    const float* Wo  = (const float*)d_in[10];
    const float* bo  = (const float*)d_in[11];

    float* out = (float*)d_out;
    float* ko  = out + (size_t)B_ * S_ * H_;
    float* vo  = ko  + (size_t)B_ * NH_ * KV_ * HD_;

    __half *xh, *xl, *wq, *wk, *wv, *wo, *qf, *kf, *vf, *ah, *al;
    cudaGetSymbolAddress((void**)&xh, sXh); cudaGetSymbolAddress((void**)&xl, sXl);
    cudaGetSymbolAddress((void**)&wq, sWq); cudaGetSymbolAddress((void**)&wk, sWk);
    cudaGetSymbolAddress((void**)&wv, sWv); cudaGetSymbolAddress((void**)&wo, sWo);
    cudaGetSymbolAddress((void**)&qf, sQf); cudaGetSymbolAddress((void**)&kf, sKf);
    cudaGetSymbolAddress((void**)&vf, sVf);
    cudaGetSymbolAddress((void**)&ah, sAh); cudaGetSymbolAddress((void**)&al, sAl);

    cudaFuncSetAttribute(gemm_qkv,
                         cudaFuncAttributeMaxDynamicSharedMemorySize, GT_SMEM);
    cudaFuncSetAttribute(gemm_out,
                         cudaFuncAttributeMaxDynamicSharedMemorySize, GT_SMEM);
    cudaFuncSetAttribute(attn_mma,
                         cudaFuncAttributeMaxDynamicSharedMemorySize, ATT_SMEM);

    // 1. splice caches into output k/v (+ fp16 copies for attention)
    copy_cache_kernel<<<8192, 256>>>((const float4*)kc, (const float4*)vc,
                                     (float4*)ko, (float4*)vo,
                                     (uint2*)kf, (uint2*)vf);

    // 2. activations: fp16 hi/lo split; weights: plain fp16
    split_h_kernel<<<8192, 256>>>((const float4*)x, (uint2*)xh, (uint2*)xl);
    convert4_kernel<<<dim3(4096, 4), 256>>>(
        (const float4*)Wq, (const float4*)Wk, (const float4*)Wv, (const float4*)Wo,
        (uint2*)wq, (uint2*)wk, (uint2*)wv, (uint2*)wo);

    // 3. fused QKV projections (fp16 2-term); q pre-scaled by 1/sqrt(HD)
    gemm_qkv<<<dim3(H_/128, M_/128, 3), 512, GT_SMEM>>>(
        xh, xl, wq, wk, wv, bq, bk, bv, ko, vo, qf, kf, vf);

    // 4. attention (fp16 operands, fp32 softmax, KV tile 64)
    attn_mma<<<dim3(S_/128, NH_, B_), 256, ATT_SMEM>>>(qf, kf, vf, msk, ah, al);

    // 5. output projection (fp16 2-term)
    gemm_out<<<dim3(H_/128, M_/128), 512, GT_SMEM>>>(ah, al, wo, bo, out);
}

// round 17
// speedup vs baseline: 1.2423x; 1.2423x over previous
#include <cuda_runtime.h>
#include <cuda_fp16.h>
#include <cstdint>

// ---------------- problem constants ----------------
#define B_     2
#define S_     2048
#define H_     2048
#define NH_    16
#define HD_    128
#define CACHE_ 2048
#define KV_    4096           // CACHE_ + S_
#define M_     4096           // B_*S_
#define KDIM_  2048           // H_

#define SCALE_ 0.08838834764831845f   // 1/sqrt(128)

// fp16 scratch (allocation-free rule: __device__ globals) — all plain fp16
static __device__ __half sXf[(size_t)M_ * KDIM_];
static __device__ __half sWq[(size_t)H_ * KDIM_];
static __device__ __half sWk[(size_t)H_ * KDIM_];
static __device__ __half sWv[(size_t)H_ * KDIM_];
static __device__ __half sWo[(size_t)H_ * KDIM_];

// attention operands / output: plain fp16
static __device__ __half sQf[(size_t)B_ * NH_ * S_ * HD_];
static __device__ __half sKf[(size_t)B_ * NH_ * KV_ * HD_];
static __device__ __half sVf[(size_t)B_ * NH_ * KV_ * HD_];
static __device__ __half sAf[(size_t)M_ * KDIM_];

// ---------------- helpers ----------------
__device__ __forceinline__ uint32_t smem_u32(const void* p) {
    uint32_t a;
    asm("{ .reg .u64 t; cvta.to.shared.u64 t, %1; cvt.u32.u64 %0, t; }" : "=r"(a) : "l"(p));
    return a;
}

#define LDSM4(r0,r1,r2,r3,addr) \
    asm volatile("ldmatrix.sync.aligned.m8n8.x4.shared.b16 {%0,%1,%2,%3}, [%4];" \
        : "=r"(r0),"=r"(r1),"=r"(r2),"=r"(r3) : "r"(addr))

#define LDSM4T(r0,r1,r2,r3,addr) \
    asm volatile("ldmatrix.sync.aligned.m8n8.x4.trans.shared.b16 {%0,%1,%2,%3}, [%4];" \
        : "=r"(r0),"=r"(r1),"=r"(r2),"=r"(r3) : "r"(addr))

#define MMA16816H(c, a, b) \
    asm volatile("mma.sync.aligned.m16n8k16.row.col.f32.f16.f16.f32 " \
        "{%0,%1,%2,%3}, {%4,%5,%6,%7}, {%8,%9}, {%0,%1,%2,%3};" \
        : "+f"((c)[0]),"+f"((c)[1]),"+f"((c)[2]),"+f"((c)[3]) \
        : "r"((a)[0]),"r"((a)[1]),"r"((a)[2]),"r"((a)[3]), "r"((b)[0]),"r"((b)[1]))

#define CP_ASYNC16(saddr, gaddr) \
    asm volatile("cp.async.cg.shared.global [%0], [%1], 16;" :: "r"(saddr), "l"(gaddr))
#define CP_COMMIT() asm volatile("cp.async.commit_group;" ::: "memory")
#define CP_WAIT0()  asm volatile("cp.async.wait_group 0;" ::: "memory")

// ---------------- cache splice (+ fp16 copies for attention) ----------------
__global__ void copy_cache_kernel(const float4* __restrict__ kc,
                                  const float4* __restrict__ vc,
                                  float4* __restrict__ ko,
                                  float4* __restrict__ vo,
                                  uint2* __restrict__ kf, uint2* __restrict__ vf) {
    int i = blockIdx.x * blockDim.x + threadIdx.x;
    int chunk = i >> 16;
    int rem   = i & 65535;
    size_t d = (size_t)chunk * (KV_ * HD_ / 4) + rem;
    float4 kk = kc[i];
    float4 vv = vc[i];
    ko[d] = kk;
    vo[d] = vv;
    __half kh4[4] = {__float2half_rn(kk.x), __float2half_rn(kk.y),
                     __float2half_rn(kk.z), __float2half_rn(kk.w)};
    __half vh4[4] = {__float2half_rn(vv.x), __float2half_rn(vv.y),
                     __float2half_rn(vv.z), __float2half_rn(vv.w)};
    kf[d] = *(uint2*)kh4;
    vf[d] = *(uint2*)vh4;
}

// ---------------- fp32 -> plain fp16 converts ----------------
__global__ void convert_kernel(const float4* __restrict__ src, uint2* __restrict__ dst) {
    int i = blockIdx.x * blockDim.x + threadIdx.x;
    float4 v = src[i];
    __half h[4] = {__float2half_rn(v.x), __float2half_rn(v.y),
                   __float2half_rn(v.z), __float2half_rn(v.w)};
    dst[i] = *(uint2*)h;
}

__global__ void convert4_kernel(const float4* s0, const float4* s1,
                                const float4* s2, const float4* s3,
                                uint2* d0, uint2* d1, uint2* d2, uint2* d3) {
    int z = blockIdx.y;
    const float4* s = (z == 0) ? s0 : (z == 1) ? s1 : (z == 2) ? s2 : s3;
    uint2* d = (z == 0) ? d0 : (z == 1) ? d1 : (z == 2) ? d2 : d3;
    int i = blockIdx.x * blockDim.x + threadIdx.x;
    float4 v = s[i];
    __half h[4] = {__float2half_rn(v.x), __float2half_rn(v.y),
                   __float2half_rn(v.z), __float2half_rn(v.w)};
    d[i] = *(uint2*)h;
}

// ---------------- mma.sync plain-fp16 GEMM core ----------------
// D = A[M,K] x B[N,K]^T + bias  (both plain fp16; 1 MMA per fragment pair)
// R8-proven geometry: GKC=32, 16 warps (512 thr), warp tile 32x32, TPAD=40.
// mode 0: fp32 dense; mode 1: fp32 KV scatter + fp16 to df; mode 2: fp16 scaled (q)
#define GKC      32
#define GNCH     (KDIM_/GKC)           // 64
#define TPAD     40
#define TILE_B   (128*TPAD*2)          // 10240
#define BUF_B    (2*TILE_B)            // 20480 (A,B)
#define GT_SMEM  (512 + 2*BUF_B)       // 41472

__device__ __forceinline__
void gemm_core(const __half* __restrict__ Af, const __half* __restrict__ Bf,
               const float* __restrict__ bias, float* __restrict__ dst,
               __half* __restrict__ df,
               int mode, int Lrow, int off, float scale,
               char* smc, int m0, int n0)
{
    float* s_bias = (float*)smc;
    const uint32_t sbase = smem_u32(smc + 512);

    const int tid = threadIdx.x;
    const int wid = tid >> 5, lane = tid & 31;
    const int wm = (wid & 3) * 32, wn = (wid >> 2) * 32;

    if (tid < 128) s_bias[tid] = bias[n0 + tid];

    const __half* srcA = Af + (size_t)m0 * KDIM_;
    const __half* srcB = Bf + (size_t)n0 * KDIM_;

    const int ld_row = tid >> 2;          // 0..127
    const int ld_c16 = tid & 3;           // 16B column
    const int aRow = wm + (lane & 15);
    const uint32_t offA0 = ((uint32_t)(aRow * TPAD + ((lane >> 4) << 3))) * 2u;
    const int bRow = wn + ((lane >> 4) << 3) + (lane & 7);
    const uint32_t offB0 = ((uint32_t)(bRow * TPAD + (((lane >> 3) & 1) << 3))) * 2u;

    float acc[2][4][4];
    #pragma unroll
    for (int i = 0; i < 2; i++)
        #pragma unroll
        for (int j = 0; j < 4; j++)
            #pragma unroll
            for (int q = 0; q < 4; q++) acc[i][j][q] = 0.f;

    auto load_chunk = [&](int buf, int c0) {
        uint32_t sb = sbase + buf * BUF_B;
        uint32_t so = (uint32_t)(ld_row * TPAD + ld_c16 * 8) * 2u;
        size_t go = (size_t)ld_row * KDIM_ + c0 + ld_c16 * 8;
        CP_ASYNC16(sb + 0 * TILE_B + so, srcA + go);
        CP_ASYNC16(sb + 1 * TILE_B + so, srcB + go);
        CP_COMMIT();
    };

    load_chunk(0, 0);

    for (int c = 0; c < GNCH; ++c) {
        CP_WAIT0();
        __syncthreads();
        if (c + 1 < GNCH) load_chunk((c + 1) & 1, (c + 1) * GKC);

        const uint32_t bb = sbase + (c & 1) * BUF_B;
        #pragma unroll
        for (int ks = 0; ks < 2; ++ks) {
            const uint32_t ko_ = ks * 32;
            uint32_t af[2][4];
            #pragma unroll
            for (int mt = 0; mt < 2; ++mt)
                LDSM4(af[mt][0], af[mt][1], af[mt][2], af[mt][3],
                      bb + 0 * TILE_B + offA0 + mt * (16 * TPAD * 2) + ko_);
            uint32_t bf[4][2];
            #pragma unroll
            for (int p = 0; p < 2; ++p) {
                uint32_t r0, r1, r2, r3;
                LDSM4(r0, r1, r2, r3,
                      bb + 1 * TILE_B + offB0 + p * (16 * TPAD * 2) + ko_);
                bf[2*p][0] = r0; bf[2*p][1] = r1; bf[2*p+1][0] = r2; bf[2*p+1][1] = r3;
            }
            #pragma unroll
            for (int mt = 0; mt < 2; ++mt)
                #pragma unroll
                for (int nt = 0; nt < 4; ++nt)
                    MMA16816H(acc[mt][nt], af[mt], bf[nt]);
        }
    }
    __syncthreads();

    #pragma unroll
    for (int mt = 0; mt < 2; ++mt) {
        #pragma unroll
        for (int nt = 0; nt < 4; ++nt) {
            float* cc = acc[mt][nt];
            int row0 = m0 + wm + mt * 16 + (lane >> 2);
            int col  = wn + nt * 8 + (lane & 3) * 2;
            float2 v0 = make_float2((cc[0] + s_bias[col]) * scale,
                                    (cc[1] + s_bias[col + 1]) * scale);
            float2 v1 = make_float2((cc[2] + s_bias[col]) * scale,
                                    (cc[3] + s_bias[col + 1]) * scale);
            if (mode == 0) {
                float* p0 = dst + (size_t)row0 * H_ + n0 + col;
                *(float2*)p0 = v0;
                *(float2*)(p0 + (size_t)8 * H_) = v1;
            } else {
                int bb_ = row0 >> 11, s = row0 & (S_ - 1);
                int head = n0 >> 7;
                size_t idx = ((size_t)(bb_ * NH_ + head) * Lrow + off + s) * HD_ + (col & (HD_ - 1));
                size_t idx1 = idx + (size_t)8 * HD_;
                if (mode == 1) {
                    *(float2*)(dst + idx)  = v0;
                    *(float2*)(dst + idx1) = v1;
                }
                *(__half2*)(df + idx)  = __floats2half2_rn(v0.x, v0.y);
                *(__half2*)(df + idx1) = __floats2half2_rn(v1.x, v1.y);
            }
        }
    }
}

__global__ __launch_bounds__(512, 1)
void gemm_qkv(const __half* __restrict__ xf,
              const __half* __restrict__ wq, const __half* __restrict__ wk,
              const __half* __restrict__ wv,
              const float* __restrict__ bq, const float* __restrict__ bk,
              const float* __restrict__ bv,
              float* __restrict__ ko, float* __restrict__ vo,
              __half* __restrict__ qf, __half* __restrict__ kf, __half* __restrict__ vf)
{
    extern __shared__ char smc[];
    const int z = blockIdx.z;
    const int n0 = blockIdx.x * 128, m0 = blockIdx.y * 128;
    if (z == 0) {
        gemm_core(xf, wq, bq, nullptr, qf, 2, S_, 0, SCALE_, smc, m0, n0);
    } else if (z == 1) {
        gemm_core(xf, wk, bk, ko, kf, 1, KV_, CACHE_, 1.0f, smc, m0, n0);
    } else {
        gemm_core(xf, wv, bv, vo, vf, 1, KV_, CACHE_, 1.0f, smc, m0, n0);
    }
}

__global__ __launch_bounds__(512, 1)
void gemm_out(const __half* __restrict__ Af, const __half* __restrict__ Bf,
              const float* __restrict__ bias, float* __restrict__ dst)
{
    extern __shared__ char smc[];
    gemm_core(Af, Bf, bias, dst, nullptr, 0, 0, 0, 1.0f,
              smc, blockIdx.y * 128, blockIdx.x * 128);
}

// ---------------- flash attention via mma.sync, plain fp16 operands ----------------
// R15-proven geometry (AKT=32), fp32 softmax, ballot-skip. Epilogue writes plain fp16.
#define AKT 32
#define QPITCH 272
#define KOFF   0
#define VOFF   8704
#define MSOFF  17408
#define STAGE_B 33792
#define QBYTES (128*QPITCH)
#define QOFF   (2*STAGE_B)
#define ATT_SMEM (2*STAGE_B + QBYTES)    // 102400

__global__ __launch_bounds__(256, 1)
void attn_mma(const __half* __restrict__ Qf,
              const __half* __restrict__ Kf,
              const __half* __restrict__ Vf,
              const float* __restrict__ Msk,
              __half* __restrict__ Of)
{
    extern __shared__ char sma[];
    const uint32_t sb = smem_u32(sma);

    const int tid = threadIdx.x;
    const int wid = tid >> 5, lane = tid & 31;
    const int qt = blockIdx.x, h = blockIdx.y, b = blockIdx.z;

    const size_t bh_q = ((size_t)(b * NH_ + h) * S_ + qt * 128) * HD_;
    const size_t bh_kv = (size_t)(b * NH_ + h) * KV_ * HD_;
    const float* Mb = Msk + ((size_t)b * S_ + qt * 128) * KV_;

    {
        int qr = tid >> 1, qc = (tid & 1) * 8;
        const __half* qp = Qf + bh_q + (size_t)qr * HD_ + qc * 8;
        uint32_t d0 = sb + QOFF + qr * QPITCH + qc * 16;
        #pragma unroll
        for (int j = 0; j < 8; j++)
            CP_ASYNC16(d0 + j * 16, qp + j * 8);
    }
    const int kv_row = tid >> 3, kv_c = tid & 7;
    const int m_row = tid >> 1, m_c = (tid & 1) * 4;
    auto issue_stage = [&](int t) {
        uint32_t st = sb + (t & 1) * STAGE_B;
        size_t go = bh_kv + (size_t)(t * AKT + kv_row) * HD_ + kv_c * 8;
        uint32_t so = st + kv_row * QPITCH + kv_c * 16;
        CP_ASYNC16(so + KOFF,       Kf + go);
        CP_ASYNC16(so + KOFF + 128, Kf + go + 64);
        CP_ASYNC16(so + VOFF,       Vf + go);
        CP_ASYNC16(so + VOFF + 128, Vf + go + 64);
        const float* mp = Mb + (size_t)m_row * KV_ + t * AKT + m_c * 4;
        uint32_t md = st + MSOFF + m_row * 128 + m_c * 16;
        #pragma unroll
        for (int j = 0; j < 4; j++)
            CP_ASYNC16(md + j * 16, mp + j * 4);
    };
    issue_stage(0);
    CP_COMMIT();

    uint32_t qF[8][4];
    float o[16][4];
    #pragma unroll
    for (int i = 0; i < 16; i++)
        #pragma unroll
        for (int j = 0; j < 4; j++) o[i][j] = 0.f;
    float m0r = -1e30f, m1r = -1e30f, l0r = 0.f, l1r = 0.f;

    const uint32_t qAoff = (uint32_t)((wid * 16 + (lane & 15)) * QPITCH + ((lane >> 4) << 3) * 2);
    const uint32_t kBrow = (uint32_t)((((lane >> 4) << 3) + (lane & 7)) * QPITCH + (((lane >> 3) & 1) << 3) * 2);
    const uint32_t vTrow = (uint32_t)(((((lane >> 3) & 1) << 3) + (lane & 7)) * QPITCH + ((lane >> 4) << 3) * 2);

    const int NIT = KV_ / AKT;   // 128
    for (int t = 0; t < NIT; ++t) {
        CP_WAIT0();
        __syncthreads();
        if (t + 1 < NIT) { issue_stage(t + 1); CP_COMMIT(); }

        if (t == 0) {
            #pragma unroll
            for (int ks = 0; ks < 8; ++ks)
                LDSM4(qF[ks][0], qF[ks][1], qF[ks][2], qF[ks][3], sb + QOFF + qAoff + ks * 32);
        }

        const uint32_t st = sb + (t & 1) * STAGE_B;

        float sacc[4][4];
        #pragma unroll
        for (int i = 0; i < 4; i++)
            #pragma unroll
            for (int j = 0; j < 4; j++) sacc[i][j] = 0.f;

        #pragma unroll
        for (int ks = 0; ks < 8; ++ks) {
            #pragma unroll
            for (int nh = 0; nh < 2; ++nh) {
                uint32_t k0, k1, k2, k3;
                LDSM4(k0, k1, k2, k3,
                      st + KOFF + kBrow + nh * 16 * QPITCH + ks * 32);
                uint32_t b0[2] = {k0, k1}, b1[2] = {k2, k3};
                MMA16816H(sacc[2*nh],   qF[ks], b0);
                MMA16816H(sacc[2*nh+1], qF[ks], b1);
            }
        }

        const uint32_t msb = st + MSOFF + (wid * 16 + (lane >> 2)) * 128 + (lane & 3) * 8;
        float p[4][4];
        float rm0 = -1e30f, rm1 = -1e30f;
        #pragma unroll
        for (int nt = 0; nt < 4; ++nt) {
            float2 mv0 = *(const float2*)(sma + (msb + nt * 32 - sb));
            float2 mv1 = *(const float2*)(sma + (msb + nt * 32 + 8 * 128 - sb));
            p[nt][0] = sacc[nt][0] + mv0.x;
            p[nt][1] = sacc[nt][1] + mv0.y;
            p[nt][2] = sacc[nt][2] + mv1.x;
            p[nt][3] = sacc[nt][3] + mv1.y;
            rm0 = fmaxf(rm0, fmaxf(p[nt][0], p[nt][1]));
            rm1 = fmaxf(rm1, fmaxf(p[nt][2], p[nt][3]));
        }
        rm0 = fmaxf(rm0, __shfl_xor_sync(0xffffffffu, rm0, 1));
        rm0 = fmaxf(rm0, __shfl_xor_sync(0xffffffffu, rm0, 2));
        rm1 = fmaxf(rm1, __shfl_xor_sync(0xffffffffu, rm1, 1));
        rm1 = fmaxf(rm1, __shfl_xor_sync(0xffffffffu, rm1, 2));
        float nm0 = fmaxf(m0r, rm0), nm1 = fmaxf(m1r, rm1);

        float rs0 = 0.f, rs1 = 0.f;
        #pragma unroll
        for (int nt = 0; nt < 4; ++nt) {
            p[nt][0] = __expf(p[nt][0] - nm0);
            p[nt][1] = __expf(p[nt][1] - nm0);
            p[nt][2] = __expf(p[nt][2] - nm1);
            p[nt][3] = __expf(p[nt][3] - nm1);
            rs0 += p[nt][0] + p[nt][1];
            rs1 += p[nt][2] + p[nt][3];
        }
        rs0 += __shfl_xor_sync(0xffffffffu, rs0, 1);
        rs0 += __shfl_xor_sync(0xffffffffu, rs0, 2);
        rs1 += __shfl_xor_sync(0xffffffffu, rs1, 1);
        rs1 += __shfl_xor_sync(0xffffffffu, rs1, 2);

        uint32_t need = __ballot_sync(0xffffffffu, (nm0 > m0r) || (nm1 > m1r));
        if (need) {
            float al0 = __expf(m0r - nm0), al1 = __expf(m1r - nm1);
            #pragma unroll
            for (int i = 0; i < 16; i++) {
                o[i][0] *= al0; o[i][1] *= al0;
                o[i][2] *= al1; o[i][3] *= al1;
            }
            l0r = l0r * al0 + rs0;
            l1r = l1r * al1 + rs1;
        } else {
            l0r += rs0;
            l1r += rs1;
        }
        m0r = nm0; m1r = nm1;

        uint32_t pF[2][4];
        #pragma unroll
        for (int ks2 = 0; ks2 < 2; ++ks2) {
            #pragma unroll
            for (int half = 0; half < 2; ++half) {
                int nt = 2 * ks2 + half;
                #pragma unroll
                for (int rr = 0; rr < 2; ++rr) {
                    __half2 hp = __floats2half2_rn(p[nt][2*rr], p[nt][2*rr+1]);
                    pF[ks2][half*2 + rr] = *(uint32_t*)&hp;
                }
            }
        }

        #pragma unroll
        for (int ks2 = 0; ks2 < 2; ++ks2) {
            #pragma unroll
            for (int vb = 0; vb < 8; ++vb) {
                uint32_t h0, h1, h2, h3;
                LDSM4T(h0, h1, h2, h3,
                       st + VOFF + vTrow + ks2 * 16 * QPITCH + vb * 32);
                uint32_t b0[2] = {h0, h1}, b1[2] = {h2, h3};
                MMA16816H(o[2*vb],   pF[ks2], b0);
                MMA16816H(o[2*vb+1], pF[ks2], b1);
            }
        }
    }

    float i0 = 1.0f / l0r, i1 = 1.0f / l1r;
    int r0 = qt * 128 + wid * 16 + (lane >> 2);
    size_t base0 = ((size_t)b * S_ + r0) * H_ + h * HD_ + (lane & 3) * 2;
    size_t base1 = base0 + (size_t)8 * H_;
    #pragma unroll
    for (int nt = 0; nt < 16; ++nt) {
        *(__half2*)(Of + base0 + nt * 8) = __floats2half2_rn(o[nt][0] * i0, o[nt][1] * i0);
        *(__half2*)(Of + base1 + nt * 8) = __floats2half2_rn(o[nt][2] * i1, o[nt][3] * i1);
    }
}

// ---------------- launch ----------------
extern "C" void kernel_launch(void* const* d_in, const int* in_sizes, int n_in,
                              void* d_out, int out_size) {
    (void)in_sizes; (void)n_in; (void)out_size;
    const float* x   = (const float*)d_in[0];
    const float* msk = (const float*)d_in[1];
    const float* kc  = (const float*)d_in[2];
    const float* vc  = (const float*)d_in[3];
    const float* Wq  = (const float*)d_in[4];
    const float* bq  = (const float*)d_in[5];
    const float* Wk  = (const float*)d_in[6];
    const float* bk  = (const float*)d_in[7];
    const float* Wv  = (const float*)d_in[8];
    const float* bv  = (const float*)d_in[9];
    const float* Wo  = (const float*)d_in[10];
    const float* bo  = (const float*)d_in[11];

    float* out = (float*)d_out;
    float* ko  = out + (size_t)B_ * S_ * H_;
    float* vo  = ko  + (size_t)B_ * NH_ * KV_ * HD_;

    __half *xf, *wq, *wk, *wv, *wo, *qf, *kf, *vf, *af;
    cudaGetSymbolAddress((void**)&xf, sXf);
    cudaGetSymbolAddress((void**)&wq, sWq); cudaGetSymbolAddress((void**)&wk, sWk);
    cudaGetSymbolAddress((void**)&wv, sWv); cudaGetSymbolAddress((void**)&wo, sWo);
    cudaGetSymbolAddress((void**)&qf, sQf); cudaGetSymbolAddress((void**)&kf, sKf);
    cudaGetSymbolAddress((void**)&vf, sVf); cudaGetSymbolAddress((void**)&af, sAf);

    cudaFuncSetAttribute(gemm_qkv,
                         cudaFuncAttributeMaxDynamicSharedMemorySize, GT_SMEM);
    cudaFuncSetAttribute(gemm_out,
                         cudaFuncAttributeMaxDynamicSharedMemorySize, GT_SMEM);
    cudaFuncSetAttribute(attn_mma,
                         cudaFuncAttributeMaxDynamicSharedMemorySize, ATT_SMEM);

    // 1. splice caches into output k/v (+ fp16 copies for attention)
    copy_cache_kernel<<<8192, 256>>>((const float4*)kc, (const float4*)vc,
                                     (float4*)ko, (float4*)vo,
                                     (uint2*)kf, (uint2*)vf);

    // 2. plain fp16 converts: x + 4 weights
    convert_kernel<<<8192, 256>>>((const float4*)x, (uint2*)xf);
    convert4_kernel<<<dim3(4096, 4), 256>>>(
        (const float4*)Wq, (const float4*)Wk, (const float4*)Wv, (const float4*)Wo,
        (uint2*)wq, (uint2*)wk, (uint2*)wv, (uint2*)wo);

    // 3. fused QKV projections (plain fp16); q pre-scaled by 1/sqrt(HD)
    gemm_qkv<<<dim3(H_/128, M_/128, 3), 512, GT_SMEM>>>(
        xf, wq, wk, wv, bq, bk, bv, ko, vo, qf, kf, vf);

    // 4. attention (fp16 operands, fp32 softmax, AKT=32 — R15-proven)
    attn_mma<<<dim3(S_/128, NH_, B_), 256, ATT_SMEM>>>(qf, kf, vf, msk, af);

    // 5. output projection (plain fp16)
    gemm_out<<<dim3(H_/128, M_/128), 512, GT_SMEM>>>(af, wo, bo, out);
}